// round 2
// baseline (speedup 1.0000x reference)
#include <cuda_runtime.h>

// Problem constants
#define B_   4
#define S_   2048
#define D_   1024
#define M_   (B_ * S_)          // 8192
#define NCH  16
#define CH   (S_ / NCH)         // 128

// ---------------- scratch (device globals; no allocation allowed) ----------
__device__ float g_avg [M_ * D_];        // 32 MB
__device__ float g_h   [M_ * D_];        // 32 MB
__device__ float g_ffn [M_ * D_];        // 32 MB
__device__ float g_gate[M_ * 2 * D_];    // 64 MB
__device__ float g_part[B_ * NCH * D_];

// ---------------- packed f32x2 helpers (Blackwell FFMA2) -------------------
__device__ __forceinline__ unsigned long long fma2(unsigned long long a,
                                                   unsigned long long b,
                                                   unsigned long long c) {
    unsigned long long d;
    asm("fma.rn.f32x2 %0, %1, %2, %3;" : "=l"(d) : "l"(a), "l"(b), "l"(c));
    return d;
}
__device__ __forceinline__ unsigned long long pack2(float x, float y) {
    unsigned long long r;
    asm("mov.b64 %0, {%1, %2};" : "=l"(r) : "f"(x), "f"(y));
    return r;
}
__device__ __forceinline__ float2 unpack2(unsigned long long v) {
    float2 r;
    asm("mov.b64 {%0, %1}, %2;" : "=f"(r.x), "=f"(r.y) : "l"(v));
    return r;
}

// ---------------- scan: causal cumulative mean ------------------------------
// phase 1: per-(b,chunk,d) partial sums
__global__ void k_partial_sums(const float* __restrict__ iV) {
    int b = blockIdx.x, ch = blockIdx.y, d = threadIdx.x;
    const float* p = iV + ((size_t)b * S_ + (size_t)ch * CH) * D_ + d;
    float s = 0.f;
#pragma unroll 8
    for (int t = 0; t < CH; t++) s += p[(size_t)t * D_];
    g_part[(b * NCH + ch) * D_ + d] = s;
}

// phase 2: exclusive prefix over chunks (per b,d)
__global__ void k_exclusive_prefix() {
    int b = blockIdx.x, d = threadIdx.x;
    float run = 0.f;
#pragma unroll
    for (int ch = 0; ch < NCH; ch++) {
        int idx = (b * NCH + ch) * D_ + d;
        float v = g_part[idx];
        g_part[idx] = run;
        run += v;
    }
}

// phase 3: in-chunk scan + divide by (s+1)
__global__ void k_cumavg(const float* __restrict__ iV) {
    int b = blockIdx.x, ch = blockIdx.y, d = threadIdx.x;
    float run = g_part[(b * NCH + ch) * D_ + d];
    const float* p = iV + ((size_t)b * S_ + (size_t)ch * CH) * D_ + d;
    float*       o = g_avg + ((size_t)b * S_ + (size_t)ch * CH) * D_ + d;
#pragma unroll 4
    for (int t = 0; t < CH; t++) {
        run += p[(size_t)t * D_];
        int s = ch * CH + t;
        o[(size_t)t * D_] = run * (1.0f / (float)(s + 1));
    }
}

// ---------------- fused GEMM (128x128x16 tile, 8x8/thread, FFMA2) ----------
// MODE: 0 = relu(x+bias)   1 = x+bias   2 = sigmoid(x+bias)
// SEL : 0 = g_avg @ B -> g_h
//       1 = g_h   @ B -> g_ffn
//       2 = concat(iQ, g_ffn) @ B -> g_gate     (A lda always 1024)
#define BM 128
#define BN 128
#define BK 16
#define LDS_ (BM + 4)

template <int MODE, int SEL>
__global__ __launch_bounds__(256, 2) void k_gemm(
    const float* __restrict__ Aparam,     // iQ for SEL==2, unused otherwise
    const float* __restrict__ Bmat,
    const float* __restrict__ bias,
    int N, int K)
{
    __shared__ float As[BK][LDS_];
    __shared__ float Bs[BK][LDS_];

    const int tid  = threadIdx.x;
    const int m0   = blockIdx.y * BM;
    const int n0   = blockIdx.x * BN;
    const int rowg = tid >> 4;       // 0..15 -> 8 rows each
    const int colg = tid & 15;       // 0..15 -> 8 cols each
    const int arow = tid >> 2;       // 0..63
    const int akq  = tid & 3;        // float4 group in K
    const int brow = tid >> 5;       // 0..7
    const int bnq  = tid & 31;       // float4 group in N

    float* C = (SEL == 0) ? g_h : (SEL == 1) ? g_ffn : g_gate;

    unsigned long long acc[8][4];
#pragma unroll
    for (int i = 0; i < 8; i++)
#pragma unroll
        for (int j = 0; j < 4; j++) acc[i][j] = 0ull;

    for (int k0 = 0; k0 < K; k0 += BK) {
        // --- select A source (virtual concat for SEL==2) ---
        const float* Ap;
        int kc;
        if (SEL == 0)      { Ap = g_avg; kc = k0; }
        else if (SEL == 1) { Ap = g_h;   kc = k0; }
        else {
            if (k0 < 1024) { Ap = Aparam; kc = k0; }
            else           { Ap = g_ffn;  kc = k0 - 1024; }
        }
        // --- load A tile (transposed into SMEM) ---
#pragma unroll
        for (int h = 0; h < 2; h++) {
            int r = arow + h * 64;
            float4 v = *(const float4*)(Ap + (size_t)(m0 + r) * 1024 + kc + akq * 4);
            As[akq * 4 + 0][r] = v.x;
            As[akq * 4 + 1][r] = v.y;
            As[akq * 4 + 2][r] = v.z;
            As[akq * 4 + 3][r] = v.w;
        }
        // --- load B tile ---
#pragma unroll
        for (int h = 0; h < 2; h++) {
            int r = brow + h * 8;
            float4 v = *(const float4*)(Bmat + (size_t)(k0 + r) * N + n0 + bnq * 4);
            *(float4*)&Bs[r][bnq * 4] = v;
        }
        __syncthreads();

#pragma unroll
        for (int kk = 0; kk < BK; kk++) {
            float4 a0 = *(const float4*)&As[kk][rowg * 8];
            float4 a1 = *(const float4*)&As[kk][rowg * 8 + 4];
            float4 b0 = *(const float4*)&Bs[kk][colg * 8];
            float4 b1 = *(const float4*)&Bs[kk][colg * 8 + 4];
            unsigned long long bp[4] = { pack2(b0.x, b0.y), pack2(b0.z, b0.w),
                                         pack2(b1.x, b1.y), pack2(b1.z, b1.w) };
            float av[8] = { a0.x, a0.y, a0.z, a0.w, a1.x, a1.y, a1.z, a1.w };
#pragma unroll
            for (int i = 0; i < 8; i++) {
                unsigned long long ap = pack2(av[i], av[i]);
#pragma unroll
                for (int j = 0; j < 4; j++) acc[i][j] = fma2(ap, bp[j], acc[i][j]);
            }
        }
        __syncthreads();
    }

    // --- epilogue ---
    const int crow = m0 + rowg * 8;
    const int ccol = n0 + colg * 8;
    float bb[8];
#pragma unroll
    for (int j = 0; j < 8; j++) bb[j] = bias[ccol + j];

#pragma unroll
    for (int i = 0; i < 8; i++) {
        float v[8];
#pragma unroll
        for (int j = 0; j < 4; j++) {
            float2 t = unpack2(acc[i][j]);
            v[2 * j] = t.x; v[2 * j + 1] = t.y;
        }
#pragma unroll
        for (int j = 0; j < 8; j++) {
            float x = v[j] + bb[j];
            if (MODE == 0)      x = fmaxf(x, 0.0f);
            else if (MODE == 2) x = 1.0f / (1.0f + expf(-x));
            v[j] = x;
        }
        float* cp = C + (size_t)(crow + i) * N + ccol;
        *(float4*)cp       = make_float4(v[0], v[1], v[2], v[3]);
        *(float4*)(cp + 4) = make_float4(v[4], v[5], v[6], v[7]);
    }
}

// ---------------- final gating combine --------------------------------------
__global__ void k_combine(const float* __restrict__ iQ, float* __restrict__ out) {
    size_t idx = (size_t)blockIdx.x * blockDim.x + threadIdx.x;  // over M_*D_/4
    size_t m = idx / (D_ / 4);
    size_t c = idx % (D_ / 4);
    float4 q  = ((const float4*)iQ)[idx];
    float4 f  = ((const float4*)g_ffn)[idx];
    float4 gi = ((const float4*)g_gate)[m * (2 * D_ / 4) + c];
    float4 gf = ((const float4*)g_gate)[m * (2 * D_ / 4) + (D_ / 4) + c];
    float4 r;
    r.x = gi.x * q.x + gf.x * f.x;
    r.y = gi.y * q.y + gf.y * f.y;
    r.z = gi.z * q.z + gf.z * f.z;
    r.w = gi.w * q.w + gf.w * f.w;
    ((float4*)out)[idx] = r;
}

// ---------------- launch -----------------------------------------------------
extern "C" void kernel_launch(void* const* d_in, const int* in_sizes, int n_in,
                              void* d_out, int out_size) {
    const float* iQ = (const float*)d_in[0];
    const float* iV = (const float*)d_in[1];
    const float* W1 = (const float*)d_in[2];
    const float* b1 = (const float*)d_in[3];
    const float* W2 = (const float*)d_in[4];
    const float* b2 = (const float*)d_in[5];
    const float* Wg = (const float*)d_in[6];
    const float* bg = (const float*)d_in[7];
    float* out = (float*)d_out;

    // causal cumulative mean -> g_avg
    k_partial_sums<<<dim3(B_, NCH), D_>>>(iV);
    k_exclusive_prefix<<<B_, D_>>>();
    k_cumavg<<<dim3(B_, NCH), D_>>>(iV);

    // h = relu(avg @ W1 + b1)
    dim3 g1(D_ / BN, M_ / BM);                   // (8, 64)
    k_gemm<0, 0><<<g1, 256>>>(nullptr, W1, b1, D_, D_);
    // ffn = h @ W2 + b2
    k_gemm<1, 1><<<g1, 256>>>(nullptr, W2, b2, D_, D_);
    // gate = sigmoid(concat(iQ, ffn) @ Wg + bg)
    dim3 g3(2 * D_ / BN, M_ / BM);               // (16, 64)
    k_gemm<2, 2><<<g3, 256>>>(iQ, Wg, bg, 2 * D_, 2 * D_);

    // out = igate*iQ + fgate*ffn
    k_combine<<<(M_ * D_ / 4) / 256, 256>>>(iQ, out);
}

// round 5
// speedup vs baseline: 1.7188x; 1.7188x over previous
#include <cuda_runtime.h>
#include <cuda_bf16.h>

#define B_   4
#define S_   2048
#define D_   1024
#define M_   (B_ * S_)          // 8192
#define NCH  16
#define CH   (S_ / NCH)         // 128

// ---------------- scratch ----------------------------------------------------
// interleaved-K bf16 operands: A-side slots (hi, lo, hi), B-side slots (hi, hi, lo)
__device__ __align__(256) __nv_bfloat16 g_q3  [(size_t)M_ * 3 * D_];
__device__ __align__(256) __nv_bfloat16 g_avg3[(size_t)M_ * 3 * D_];
__device__ __align__(256) __nv_bfloat16 g_h3  [(size_t)M_ * 3 * D_];
__device__ __align__(256) __nv_bfloat16 g_ffn3[(size_t)M_ * 3 * D_];
__device__ __align__(256) __nv_bfloat16 g_W13 [(size_t)D_ * 3 * D_];        // [N, 3K]
__device__ __align__(256) __nv_bfloat16 g_W23 [(size_t)D_ * 3 * D_];
__device__ __align__(256) __nv_bfloat16 g_Wg3 [(size_t)2 * D_ * 6 * D_];
__device__ __align__(256) float g_ffn [(size_t)M_ * D_];
__device__ __align__(256) float g_gate[(size_t)M_ * 2 * D_];
__device__ float g_part[B_ * NCH * D_];

// ---------------- helpers ----------------------------------------------------
__device__ __forceinline__ unsigned smem_u32(const void* p) {
    unsigned r;
    asm("{ .reg .u64 t; cvta.to.shared.u64 t, %1; cvt.u32.u64 %0, t; }" : "=r"(r) : "l"(p));
    return r;
}
__device__ __forceinline__ void split3(float x, unsigned short& h, unsigned short& l) {
    __nv_bfloat16 hb = __float2bfloat16_rn(x);
    h = __bfloat16_as_ushort(hb);
    l = __bfloat16_as_ushort(__float2bfloat16_rn(x - __bfloat162float(hb)));
}
__device__ __forceinline__ void ldsm4(unsigned& r0, unsigned& r1, unsigned& r2, unsigned& r3,
                                      unsigned addr) {
    asm volatile("ldmatrix.sync.aligned.m8n8.x4.shared.b16 {%0,%1,%2,%3}, [%4];"
                 : "=r"(r0), "=r"(r1), "=r"(r2), "=r"(r3) : "r"(addr));
}
__device__ __forceinline__ void mma16816(float* c, unsigned a0, unsigned a1, unsigned a2,
                                         unsigned a3, unsigned b0, unsigned b1) {
    asm volatile(
        "mma.sync.aligned.m16n8k16.row.col.f32.bf16.bf16.f32 "
        "{%0,%1,%2,%3}, {%4,%5,%6,%7}, {%8,%9}, {%0,%1,%2,%3};"
        : "+f"(c[0]), "+f"(c[1]), "+f"(c[2]), "+f"(c[3])
        : "r"(a0), "r"(a1), "r"(a2), "r"(a3), "r"(b0), "r"(b1));
}

// ---------------- scan: causal cumulative mean -------------------------------
__global__ void k_partial_sums(const float* __restrict__ iV) {
    int b = blockIdx.x, ch = blockIdx.y, d = threadIdx.x;
    const float* p = iV + ((size_t)b * S_ + (size_t)ch * CH) * D_ + d;
    float s = 0.f;
#pragma unroll 8
    for (int t = 0; t < CH; t++) s += p[(size_t)t * D_];
    g_part[(b * NCH + ch) * D_ + d] = s;
}

__global__ void k_exclusive_prefix() {
    int b = blockIdx.x, d = threadIdx.x;
    float run = 0.f;
#pragma unroll
    for (int ch = 0; ch < NCH; ch++) {
        int idx = (b * NCH + ch) * D_ + d;
        float v = g_part[idx];
        g_part[idx] = run;
        run += v;
    }
}

__global__ void k_cumavg(const float* __restrict__ iV) {
    int b = blockIdx.x, ch = blockIdx.y, d = threadIdx.x;
    float run = g_part[(b * NCH + ch) * D_ + d];
    const float* p = iV + ((size_t)b * S_ + (size_t)ch * CH) * D_ + d;
    size_t mrow = (size_t)b * S_ + (size_t)ch * CH;
#pragma unroll 4
    for (int t = 0; t < CH; t++) {
        run += p[(size_t)t * D_];
        int s = ch * CH + t;
        float x = run * (1.0f / (float)(s + 1));
        unsigned short h, l;
        split3(x, h, l);
        __nv_bfloat16* o = g_avg3 + (mrow + t) * (3 * D_) + 3 * d;
        o[0] = __ushort_as_bfloat16(h);
        o[1] = __ushort_as_bfloat16(l);
        o[2] = __ushort_as_bfloat16(h);
    }
}

// ---------------- conversions ------------------------------------------------
__global__ void k_convert_iQ(const float* __restrict__ iQ) {
    size_t idx = (size_t)blockIdx.x * blockDim.x + threadIdx.x;   // over M_*D_
    float x = iQ[idx];
    unsigned short h, l;
    split3(x, h, l);
    size_t m = idx / D_, d = idx % D_;
    __nv_bfloat16* o = g_q3 + m * (3 * D_) + 3 * d;
    o[0] = __ushort_as_bfloat16(h);
    o[1] = __ushort_as_bfloat16(l);
    o[2] = __ushort_as_bfloat16(h);
}

// W [K,N] fp32 -> W3 [N, 3K] bf16 slots (hi, hi, lo), via smem transpose
__global__ void k_convert_W(const float* __restrict__ W, __nv_bfloat16* __restrict__ W3,
                            int K, int N) {
    __shared__ float t[32][33];
    int n0 = blockIdx.x * 32, k0 = blockIdx.y * 32;
    t[threadIdx.y][threadIdx.x] = W[(size_t)(k0 + threadIdx.y) * N + n0 + threadIdx.x];
    __syncthreads();
    int n = n0 + threadIdx.y, k = k0 + threadIdx.x;
    float x = t[threadIdx.x][threadIdx.y];
    unsigned short h, l;
    split3(x, h, l);
    __nv_bfloat16* o = W3 + (size_t)n * (3 * K) + 3 * k;
    o[0] = __ushort_as_bfloat16(h);
    o[1] = __ushort_as_bfloat16(h);
    o[2] = __ushort_as_bfloat16(l);
}

// ---------------- HMMA bf16 GEMM ----------------------------------------------
// C[m,n] = sum_k' A3[m,k'] * B3[n,k']  (both K-major interleaved bf16)
// SEL 0: A=g_avg3 @ g_W13 -> relu+b1 -> g_h3
// SEL 1: A=g_h3   @ g_W23 -> +b2    -> g_ffn (fp32) + g_ffn3
// SEL 2: A=concat(g_q3, g_ffn3) @ g_Wg3 -> sigmoid+bg -> g_gate (fp32)
#define BK 64            // bf16 per K block = 128 B row
#define STAGES 3
#define STG_BYTES (2 * 128 * 128)          // A tile + B tile per stage = 32 KB
#define SMEM_DYN (STAGES * STG_BYTES)

template <int SEL>
__global__ __launch_bounds__(256)
void k_gemm_mma(const __nv_bfloat16* __restrict__ A0,
                const __nv_bfloat16* __restrict__ A1,
                const __nv_bfloat16* __restrict__ Bw,
                const float* __restrict__ bias,
                int N, int K3)
{
    extern __shared__ __align__(1024) char dsmem[];
    const unsigned sbase = smem_u32(dsmem);

    const int tid = threadIdx.x;
    const int warp = tid >> 5, lid = tid & 31;
    const int wm = warp >> 2;            // 0..1 -> 64 rows each
    const int wn = warp & 3;             // 0..3 -> 32 cols each
    const int m0 = blockIdx.y * 128;
    const int n0 = blockIdx.x * 128;
    const int NB = K3 / BK;

    // ---- loader indices: thread t loads 4x16B of A and 4x16B of B ----
    const int lrow = tid >> 1;           // 0..127
    const int lcb  = (tid & 1) * 4;      // chunk base 0 or 4
    const int lswz = lrow & 7;

    float acc[4][4][4];
#pragma unroll
    for (int i = 0; i < 4; i++)
#pragma unroll
        for (int j = 0; j < 4; j++)
#pragma unroll
            for (int k = 0; k < 4; k++) acc[i][j][k] = 0.f;

    auto load_blk = [&](int kb, int stage) {
        unsigned sA = sbase + stage * STG_BYTES;
        unsigned sB = sA + 128 * 128;
        // A row (all A operands have row stride 3*D_ bf16)
        const __nv_bfloat16* Arow;
        if (SEL == 2 && kb >= 48)
            Arow = A1 + (size_t)(m0 + lrow) * (3 * D_) + (size_t)(kb - 48) * BK;
        else
            Arow = A0 + (size_t)(m0 + lrow) * (3 * D_) + (size_t)kb * BK;
        unsigned long long ag = (unsigned long long)Arow;
        unsigned asm_ = sA + lrow * 128;
#pragma unroll
        for (int i = 0; i < 4; i++) {
            int c = lcb + i;
            asm volatile("cp.async.cg.shared.global [%0], [%1], 16;"
                         :: "r"(asm_ + (unsigned)((c ^ lswz) << 4)), "l"(ag + c * 16) : "memory");
        }
        const __nv_bfloat16* Brow = Bw + (size_t)(n0 + lrow) * K3 + (size_t)kb * BK;
        unsigned long long bg2 = (unsigned long long)Brow;
        unsigned bsm = sB + lrow * 128;
#pragma unroll
        for (int i = 0; i < 4; i++) {
            int c = lcb + i;
            asm volatile("cp.async.cg.shared.global [%0], [%1], 16;"
                         :: "r"(bsm + (unsigned)((c ^ lswz) << 4)), "l"(bg2 + c * 16) : "memory");
        }
        asm volatile("cp.async.commit_group;" ::: "memory");
    };

    // ---- fragment addressing (constant per thread) ----
    int arow[4], brow[2];
#pragma unroll
    for (int mt = 0; mt < 4; mt++)
        arow[mt] = wm * 64 + mt * 16 + (lid & 7) + ((lid >> 3) & 1) * 8;
    const int ahi = lid >> 4;            // chunk +0/+1 within k16
#pragma unroll
    for (int p = 0; p < 2; p++)
        brow[p] = wn * 32 + p * 16 + (lid & 7) + (lid >> 4) * 8;
    const int bhi = (lid >> 3) & 1;

    // ---- prologue ----
#pragma unroll
    for (int s = 0; s < STAGES - 1; s++) load_blk(s, s);

    for (int kb = 0; kb < NB; kb++) {
        asm volatile("cp.async.wait_group %0;" :: "n"(STAGES - 2) : "memory");
        __syncthreads();
        if (kb + STAGES - 1 < NB) load_blk(kb + STAGES - 1, (kb + STAGES - 1) % STAGES);

        unsigned sA = sbase + (kb % STAGES) * STG_BYTES;
        unsigned sB = sA + 128 * 128;
#pragma unroll
        for (int ks = 0; ks < 4; ks++) {
            unsigned a[4][4];
#pragma unroll
            for (int mt = 0; mt < 4; mt++) {
                unsigned addr = sA + arow[mt] * 128 +
                                (unsigned)(((2 * ks + ahi) ^ (arow[mt] & 7)) << 4);
                ldsm4(a[mt][0], a[mt][1], a[mt][2], a[mt][3], addr);
            }
            unsigned b[2][4];
#pragma unroll
            for (int p = 0; p < 2; p++) {
                unsigned addr = sB + brow[p] * 128 +
                                (unsigned)(((2 * ks + bhi) ^ (brow[p] & 7)) << 4);
                ldsm4(b[p][0], b[p][1], b[p][2], b[p][3], addr);
            }
#pragma unroll
            for (int mt = 0; mt < 4; mt++)
#pragma unroll
                for (int nt = 0; nt < 4; nt++)
                    mma16816(acc[mt][nt], a[mt][0], a[mt][1], a[mt][2], a[mt][3],
                             b[nt >> 1][(nt & 1) * 2], b[nt >> 1][(nt & 1) * 2 + 1]);
        }
    }

    // ---- epilogue (fragment layout: c0,c1 = (row, n..n+1), c2,c3 = row+8) ----
    const int gid = lid >> 2, tig = lid & 3;
#pragma unroll
    for (int mt = 0; mt < 4; mt++) {
#pragma unroll
        for (int r2 = 0; r2 < 2; r2++) {
            const int m = m0 + wm * 64 + mt * 16 + gid + r2 * 8;
#pragma unroll
            for (int nt = 0; nt < 4; nt++) {
                const int n = n0 + wn * 32 + nt * 8 + 2 * tig;
                float2 bb = *(const float2*)(bias + n);
                float v0 = acc[mt][nt][r2 * 2 + 0] + bb.x;
                float v1 = acc[mt][nt][r2 * 2 + 1] + bb.y;
                if (SEL == 0) {
                    v0 = fmaxf(v0, 0.f); v1 = fmaxf(v1, 0.f);
                    unsigned short h0, l0, h1, l1;
                    split3(v0, h0, l0); split3(v1, h1, l1);
                    unsigned* dst = (unsigned*)(g_h3 + (size_t)m * (3 * D_) + 3 * n);
                    dst[0] = (unsigned)h0 | ((unsigned)l0 << 16);
                    dst[1] = (unsigned)h0 | ((unsigned)h1 << 16);
                    dst[2] = (unsigned)l1 | ((unsigned)h1 << 16);
                } else if (SEL == 1) {
                    *(float2*)(g_ffn + (size_t)m * D_ + n) = make_float2(v0, v1);
                    unsigned short h0, l0, h1, l1;
                    split3(v0, h0, l0); split3(v1, h1, l1);
                    unsigned* dst = (unsigned*)(g_ffn3 + (size_t)m * (3 * D_) + 3 * n);
                    dst[0] = (unsigned)h0 | ((unsigned)l0 << 16);
                    dst[1] = (unsigned)h0 | ((unsigned)h1 << 16);
                    dst[2] = (unsigned)l1 | ((unsigned)h1 << 16);
                } else {
                    v0 = 1.0f / (1.0f + __expf(-v0));
                    v1 = 1.0f / (1.0f + __expf(-v1));
                    *(float2*)(g_gate + (size_t)m * (2 * D_) + n) = make_float2(v0, v1);
                }
            }
        }
    }
}

// ---------------- final gating combine ---------------------------------------
__global__ void k_combine(const float* __restrict__ iQ, float* __restrict__ out) {
    size_t idx = (size_t)blockIdx.x * blockDim.x + threadIdx.x;  // over M_*D_/4
    size_t m = idx / (D_ / 4);
    size_t c = idx % (D_ / 4);
    float4 q  = ((const float4*)iQ)[idx];
    float4 f  = ((const float4*)g_ffn)[idx];
    float4 gi = ((const float4*)g_gate)[m * (2 * D_ / 4) + c];
    float4 gf = ((const float4*)g_gate)[m * (2 * D_ / 4) + (D_ / 4) + c];
    float4 r;
    r.x = gi.x * q.x + gf.x * f.x;
    r.y = gi.y * q.y + gf.y * f.y;
    r.z = gi.z * q.z + gf.z * f.z;
    r.w = gi.w * q.w + gf.w * f.w;
    ((float4*)out)[idx] = r;
}

// ---------------- launch ------------------------------------------------------
extern "C" void kernel_launch(void* const* d_in, const int* in_sizes, int n_in,
                              void* d_out, int out_size) {
    const float* iQ = (const float*)d_in[0];
    const float* iV = (const float*)d_in[1];
    const float* W1 = (const float*)d_in[2];
    const float* b1 = (const float*)d_in[3];
    const float* W2 = (const float*)d_in[4];
    const float* b2 = (const float*)d_in[5];
    const float* Wg = (const float*)d_in[6];
    const float* bg = (const float*)d_in[7];
    float* out = (float*)d_out;

    cudaFuncSetAttribute(k_gemm_mma<0>, cudaFuncAttributeMaxDynamicSharedMemorySize, SMEM_DYN);
    cudaFuncSetAttribute(k_gemm_mma<1>, cudaFuncAttributeMaxDynamicSharedMemorySize, SMEM_DYN);
    cudaFuncSetAttribute(k_gemm_mma<2>, cudaFuncAttributeMaxDynamicSharedMemorySize, SMEM_DYN);

    __nv_bfloat16 *w13, *w23, *wg3, *q3, *avg3, *h3, *ffn3;
    cudaGetSymbolAddress((void**)&w13,  g_W13);
    cudaGetSymbolAddress((void**)&w23,  g_W23);
    cudaGetSymbolAddress((void**)&wg3,  g_Wg3);
    cudaGetSymbolAddress((void**)&q3,   g_q3);
    cudaGetSymbolAddress((void**)&avg3, g_avg3);
    cudaGetSymbolAddress((void**)&h3,   g_h3);
    cudaGetSymbolAddress((void**)&ffn3, g_ffn3);

    // operand prep
    k_convert_iQ<<<(M_ * D_) / 256, 256>>>(iQ);
    k_convert_W<<<dim3(D_ / 32, D_ / 32), dim3(32, 32)>>>(W1, w13, D_, D_);
    k_convert_W<<<dim3(D_ / 32, D_ / 32), dim3(32, 32)>>>(W2, w23, D_, D_);
    k_convert_W<<<dim3(2 * D_ / 32, 2 * D_ / 32), dim3(32, 32)>>>(Wg, wg3, 2 * D_, 2 * D_);

    // causal cumulative mean -> g_avg3
    k_partial_sums<<<dim3(B_, NCH), D_>>>(iV);
    k_exclusive_prefix<<<B_, D_>>>();
    k_cumavg<<<dim3(B_, NCH), D_>>>(iV);

    // h = relu(avg @ W1 + b1)            [K'=3072]
    k_gemm_mma<0><<<dim3(D_ / 128, M_ / 128), 256, SMEM_DYN>>>(avg3, nullptr, w13, b1, D_, 3 * D_);
    // ffn = h @ W2 + b2                  [K'=3072]
    k_gemm_mma<1><<<dim3(D_ / 128, M_ / 128), 256, SMEM_DYN>>>(h3, nullptr, w23, b2, D_, 3 * D_);
    // gate = sigmoid(concat(iQ,ffn) @ Wg + bg)   [K'=6144]
    k_gemm_mma<2><<<dim3(2 * D_ / 128, M_ / 128), 256, SMEM_DYN>>>(q3, ffn3, wg3, bg, 2 * D_, 6 * D_);

    // out = igate*iQ + fgate*ffn
    k_combine<<<(M_ * D_ / 4) / 256, 256>>>(iQ, out);
}

// round 6
// speedup vs baseline: 1.8672x; 1.0863x over previous
#include <cuda_runtime.h>
#include <cuda_bf16.h>

#define B_   4
#define S_   2048
#define D_   1024
#define M_   (B_ * S_)          // 8192
#define NCH  16
#define CH   (S_ / NCH)         // 128

// ---------------- scratch ----------------------------------------------------
// interleaved-K bf16 operands: A-side slots (hi, lo, hi), B-side slots (hi, hi, lo)
__device__ __align__(256) __nv_bfloat16 g_q3  [(size_t)M_ * 3 * D_];
__device__ __align__(256) __nv_bfloat16 g_avg3[(size_t)M_ * 3 * D_];
__device__ __align__(256) __nv_bfloat16 g_h3  [(size_t)M_ * 3 * D_];
__device__ __align__(256) __nv_bfloat16 g_ffn3[(size_t)M_ * 3 * D_];
__device__ __align__(256) __nv_bfloat16 g_W13 [(size_t)D_ * 3 * D_];        // [N, 3K]
__device__ __align__(256) __nv_bfloat16 g_W23 [(size_t)D_ * 3 * D_];
__device__ __align__(256) __nv_bfloat16 g_Wg3 [(size_t)2 * D_ * 6 * D_];
__device__ __align__(256) float g_ffn [(size_t)M_ * D_];
__device__ float g_part[B_ * NCH * D_];

// ---------------- helpers ----------------------------------------------------
__device__ __forceinline__ unsigned smem_u32(const void* p) {
    unsigned r;
    asm("{ .reg .u64 t; cvta.to.shared.u64 t, %1; cvt.u32.u64 %0, t; }" : "=r"(r) : "l"(p));
    return r;
}
__device__ __forceinline__ void split3(float x, unsigned short& h, unsigned short& l) {
    __nv_bfloat16 hb = __float2bfloat16_rn(x);
    h = __bfloat16_as_ushort(hb);
    l = __bfloat16_as_ushort(__float2bfloat16_rn(x - __bfloat162float(hb)));
}
__device__ __forceinline__ void ldsm4(unsigned& r0, unsigned& r1, unsigned& r2, unsigned& r3,
                                      unsigned addr) {
    asm volatile("ldmatrix.sync.aligned.m8n8.x4.shared.b16 {%0,%1,%2,%3}, [%4];"
                 : "=r"(r0), "=r"(r1), "=r"(r2), "=r"(r3) : "r"(addr));
}
__device__ __forceinline__ void mma16816(float* c, unsigned a0, unsigned a1, unsigned a2,
                                         unsigned a3, unsigned b0, unsigned b1) {
    asm volatile(
        "mma.sync.aligned.m16n8k16.row.col.f32.bf16.bf16.f32 "
        "{%0,%1,%2,%3}, {%4,%5,%6,%7}, {%8,%9}, {%0,%1,%2,%3};"
        : "+f"(c[0]), "+f"(c[1]), "+f"(c[2]), "+f"(c[3])
        : "r"(a0), "r"(a1), "r"(a2), "r"(a3), "r"(b0), "r"(b1));
}

// ---------------- scan: causal cumulative mean -------------------------------
__global__ void k_partial_sums(const float* __restrict__ iV) {
    int b = blockIdx.x, ch = blockIdx.y, d = threadIdx.x;
    const float* p = iV + ((size_t)b * S_ + (size_t)ch * CH) * D_ + d;
    float s = 0.f;
#pragma unroll 8
    for (int t = 0; t < CH; t++) s += p[(size_t)t * D_];
    g_part[(b * NCH + ch) * D_ + d] = s;
}

__global__ void k_exclusive_prefix() {
    int b = blockIdx.x, d = threadIdx.x;
    float run = 0.f;
#pragma unroll
    for (int ch = 0; ch < NCH; ch++) {
        int idx = (b * NCH + ch) * D_ + d;
        float v = g_part[idx];
        g_part[idx] = run;
        run += v;
    }
}

__global__ void k_cumavg(const float* __restrict__ iV) {
    int b = blockIdx.x, ch = blockIdx.y, d = threadIdx.x;
    float run = g_part[(b * NCH + ch) * D_ + d];
    const float* p = iV + ((size_t)b * S_ + (size_t)ch * CH) * D_ + d;
    size_t mrow = (size_t)b * S_ + (size_t)ch * CH;
#pragma unroll 4
    for (int t = 0; t < CH; t++) {
        run += p[(size_t)t * D_];
        int s = ch * CH + t;
        float x = run * (1.0f / (float)(s + 1));
        unsigned short h, l;
        split3(x, h, l);
        __nv_bfloat16* o = g_avg3 + (mrow + t) * (3 * D_) + 3 * d;
        o[0] = __ushort_as_bfloat16(h);
        o[1] = __ushort_as_bfloat16(l);
        o[2] = __ushort_as_bfloat16(h);
    }
}

// ---------------- conversions ------------------------------------------------
__global__ void k_convert_iQ(const float* __restrict__ iQ) {
    size_t idx = (size_t)blockIdx.x * blockDim.x + threadIdx.x;   // over M_*D_
    float x = iQ[idx];
    unsigned short h, l;
    split3(x, h, l);
    size_t m = idx / D_, d = idx % D_;
    __nv_bfloat16* o = g_q3 + m * (3 * D_) + 3 * d;
    o[0] = __ushort_as_bfloat16(h);
    o[1] = __ushort_as_bfloat16(l);
    o[2] = __ushort_as_bfloat16(h);
}

// W [K,N] fp32 -> W3 [N, 3K] bf16 slots (hi, hi, lo). 64x64 tile, 256 threads.
__global__ __launch_bounds__(256) void k_convert_W(const float* __restrict__ W,
                                                   __nv_bfloat16* __restrict__ W3,
                                                   int K, int N) {
    __shared__ float t[64][65];
    const int tid = threadIdx.x;
    const int n0 = blockIdx.x * 64, k0 = blockIdx.y * 64;
    {
        const int r = tid >> 4;          // 0..15
        const int c4 = tid & 15;         // 0..15
#pragma unroll
        for (int i = 0; i < 4; i++) {
            int k = r + 16 * i;
            float4 v = *(const float4*)(W + (size_t)(k0 + k) * N + n0 + 4 * c4);
            t[k][4 * c4 + 0] = v.x;
            t[k][4 * c4 + 1] = v.y;
            t[k][4 * c4 + 2] = v.z;
            t[k][4 * c4 + 3] = v.w;
        }
    }
    __syncthreads();
    const int n = tid >> 2;              // 0..63
    const int kq = tid & 3;              // 0..3  (16 k's each)
    unsigned short s[48];
#pragma unroll
    for (int j = 0; j < 16; j++) {
        unsigned short h, l;
        split3(t[16 * kq + j][n], h, l);
        s[3 * j + 0] = h; s[3 * j + 1] = h; s[3 * j + 2] = l;
    }
    unsigned w[24];
#pragma unroll
    for (int i = 0; i < 24; i++)
        w[i] = (unsigned)s[2 * i] | ((unsigned)s[2 * i + 1] << 16);
    uint4* dst = (uint4*)(W3 + (size_t)(n0 + n) * (3 * K) + 3 * (k0 + 16 * kq));
#pragma unroll
    for (int i = 0; i < 6; i++)
        dst[i] = make_uint4(w[4 * i], w[4 * i + 1], w[4 * i + 2], w[4 * i + 3]);
}

// ---------------- HMMA bf16 GEMM ----------------------------------------------
// SEL 0: g_avg3 @ g_W13 -> relu+b1 -> g_h3
// SEL 1: g_h3   @ g_W23 -> +b2    -> g_ffn (fp32) + g_ffn3
// SEL 2: concat(g_q3, g_ffn3) @ g_Wg3(paired cols n, n+1024) -> sigmoid ->
//        smem exchange -> out = igate*iQ + fgate*ffn      (fully fused)
#define BK 64            // bf16 per K block = 128 B row
#define STAGES 3
#define STG_BYTES (2 * 128 * 128)          // A tile + B tile per stage = 32 KB
#define SMEM_DYN (STAGES * STG_BYTES)      // 96 KB (also covers 128x132 f32 exchange)

template <int SEL>
__global__ __launch_bounds__(256, 2)
void k_gemm_mma(const __nv_bfloat16* __restrict__ A0,
                const __nv_bfloat16* __restrict__ A1,
                const __nv_bfloat16* __restrict__ Bw,
                const float* __restrict__ bias,
                int N, int K3,
                const float* __restrict__ iQf,
                float* __restrict__ out)
{
    extern __shared__ __align__(1024) char dsmem[];
    const unsigned sbase = smem_u32(dsmem);

    const int tid = threadIdx.x;
    const int warp = tid >> 5, lid = tid & 31;
    const int wm = warp >> 2;            // 0..1 -> 64 rows each
    const int wn = warp & 3;             // 0..3 -> 32 cols each
    const int m0 = blockIdx.y * 128;
    const int n0 = blockIdx.x * 128;     // internal tile col base (SEL0/1)
    const int cg0 = blockIdx.x * 64;     // SEL2: gate col group base
    const int NB = K3 / BK;

    const int lrow = tid >> 1;           // 0..127
    const int lcb  = (tid & 1) * 4;      // chunk base 0 or 4
    const int lswz = lrow & 7;

    float acc[4][4][4];
#pragma unroll
    for (int i = 0; i < 4; i++)
#pragma unroll
        for (int j = 0; j < 4; j++)
#pragma unroll
            for (int k = 0; k < 4; k++) acc[i][j][k] = 0.f;

    auto load_blk = [&](int kb, int stage) {
        unsigned sA = sbase + stage * STG_BYTES;
        unsigned sB = sA + 128 * 128;
        const __nv_bfloat16* Arow;
        if (SEL == 2 && kb >= 48)
            Arow = A1 + (size_t)(m0 + lrow) * (3 * D_) + (size_t)(kb - 48) * BK;
        else
            Arow = A0 + (size_t)(m0 + lrow) * (3 * D_) + (size_t)kb * BK;
        unsigned long long ag = (unsigned long long)Arow;
        unsigned asm_ = sA + lrow * 128;
#pragma unroll
        for (int i = 0; i < 4; i++) {
            int c = lcb + i;
            asm volatile("cp.async.cg.shared.global [%0], [%1], 16;"
                         :: "r"(asm_ + (unsigned)((c ^ lswz) << 4)), "l"(ag + c * 16) : "memory");
        }
        // B row: SEL2 packs rows [cg0, cg0+64) then [1024+cg0, 1024+cg0+64)
        int gn;
        if (SEL == 2) gn = (lrow < 64) ? (cg0 + lrow) : (1024 + cg0 + lrow - 64);
        else          gn = n0 + lrow;
        const __nv_bfloat16* Brow = Bw + (size_t)gn * K3 + (size_t)kb * BK;
        unsigned long long bg2 = (unsigned long long)Brow;
        unsigned bsm = sB + lrow * 128;
#pragma unroll
        for (int i = 0; i < 4; i++) {
            int c = lcb + i;
            asm volatile("cp.async.cg.shared.global [%0], [%1], 16;"
                         :: "r"(bsm + (unsigned)((c ^ lswz) << 4)), "l"(bg2 + c * 16) : "memory");
        }
        asm volatile("cp.async.commit_group;" ::: "memory");
    };

    // ---- fragment addressing ----
    int arow[4], brow[2];
#pragma unroll
    for (int mt = 0; mt < 4; mt++)
        arow[mt] = wm * 64 + mt * 16 + (lid & 7) + ((lid >> 3) & 1) * 8;
    const int ahi = lid >> 4;
#pragma unroll
    for (int p = 0; p < 2; p++)
        brow[p] = wn * 32 + p * 16 + (lid & 7) + (lid >> 4) * 8;
    const int bhi = (lid >> 3) & 1;

    // ---- prologue ----
#pragma unroll
    for (int s = 0; s < STAGES - 1; s++) load_blk(s, s);

    for (int kb = 0; kb < NB; kb++) {
        asm volatile("cp.async.wait_group %0;" :: "n"(STAGES - 2) : "memory");
        __syncthreads();
        if (kb + STAGES - 1 < NB) load_blk(kb + STAGES - 1, (kb + STAGES - 1) % STAGES);

        unsigned sA = sbase + (kb % STAGES) * STG_BYTES;
        unsigned sB = sA + 128 * 128;
#pragma unroll
        for (int ks = 0; ks < 4; ks++) {
            unsigned a[4][4];
#pragma unroll
            for (int mt = 0; mt < 4; mt++) {
                unsigned addr = sA + arow[mt] * 128 +
                                (unsigned)(((2 * ks + ahi) ^ (arow[mt] & 7)) << 4);
                ldsm4(a[mt][0], a[mt][1], a[mt][2], a[mt][3], addr);
            }
            unsigned b[2][4];
#pragma unroll
            for (int p = 0; p < 2; p++) {
                unsigned addr = sB + brow[p] * 128 +
                                (unsigned)(((2 * ks + bhi) ^ (brow[p] & 7)) << 4);
                ldsm4(b[p][0], b[p][1], b[p][2], b[p][3], addr);
            }
#pragma unroll
            for (int mt = 0; mt < 4; mt++)
#pragma unroll
                for (int nt = 0; nt < 4; nt++)
                    mma16816(acc[mt][nt], a[mt][0], a[mt][1], a[mt][2], a[mt][3],
                             b[nt >> 1][(nt & 1) * 2], b[nt >> 1][(nt & 1) * 2 + 1]);
        }
    }

    // ---- epilogue ----
    const int gid = lid >> 2, tig = lid & 3;

    if (SEL == 2) {
        // gate exchange through smem (pipeline smem is done after last k-loop sync)
        __syncthreads();
        float* gsm = (float*)dsmem;        // [128][132]
#pragma unroll
        for (int mt = 0; mt < 4; mt++) {
#pragma unroll
            for (int r2 = 0; r2 < 2; r2++) {
                const int ml = wm * 64 + mt * 16 + gid + r2 * 8;
#pragma unroll
                for (int nt = 0; nt < 4; nt++) {
                    const int nl = wn * 32 + nt * 8 + 2 * tig;
                    const int gcol = (nl < 64) ? (cg0 + nl) : (1024 + cg0 + nl - 64);
                    float2 bb = *(const float2*)(bias + gcol);
                    float v0 = acc[mt][nt][r2 * 2 + 0] + bb.x;
                    float v1 = acc[mt][nt][r2 * 2 + 1] + bb.y;
                    v0 = 1.0f / (1.0f + __expf(-v0));
                    v1 = 1.0f / (1.0f + __expf(-v1));
                    gsm[ml * 132 + nl]     = v0;
                    gsm[ml * 132 + nl + 1] = v1;
                }
            }
        }
        __syncthreads();
        // out[m, cg0 + c] = gi*iQ + gf*ffn   for c in [0,64)
        const int c4 = tid & 15;            // float4 col group 0..15
        const int r0 = tid >> 4;            // 0..15
#pragma unroll
        for (int i = 0; i < 8; i++) {
            const int r = r0 + 16 * i;
            const int col = 4 * c4;
            const size_t gidx = (size_t)(m0 + r) * D_ + cg0 + col;
            float4 q = *(const float4*)(iQf + gidx);
            float4 f = *(const float4*)(g_ffn + gidx);
            float4 gi = *(const float4*)&gsm[r * 132 + col];
            float4 gf = *(const float4*)&gsm[r * 132 + 64 + col];
            float4 o;
            o.x = gi.x * q.x + gf.x * f.x;
            o.y = gi.y * q.y + gf.y * f.y;
            o.z = gi.z * q.z + gf.z * f.z;
            o.w = gi.w * q.w + gf.w * f.w;
            *(float4*)(out + gidx) = o;
        }
        return;
    }

#pragma unroll
    for (int mt = 0; mt < 4; mt++) {
#pragma unroll
        for (int r2 = 0; r2 < 2; r2++) {
            const int m = m0 + wm * 64 + mt * 16 + gid + r2 * 8;
#pragma unroll
            for (int nt = 0; nt < 4; nt++) {
                const int n = n0 + wn * 32 + nt * 8 + 2 * tig;
                float2 bb = *(const float2*)(bias + n);
                float v0 = acc[mt][nt][r2 * 2 + 0] + bb.x;
                float v1 = acc[mt][nt][r2 * 2 + 1] + bb.y;
                if (SEL == 0) {
                    v0 = fmaxf(v0, 0.f); v1 = fmaxf(v1, 0.f);
                    unsigned short h0, l0, h1, l1;
                    split3(v0, h0, l0); split3(v1, h1, l1);
                    unsigned* dst = (unsigned*)(g_h3 + (size_t)m * (3 * D_) + 3 * n);
                    dst[0] = (unsigned)h0 | ((unsigned)l0 << 16);
                    dst[1] = (unsigned)h0 | ((unsigned)h1 << 16);
                    dst[2] = (unsigned)l1 | ((unsigned)h1 << 16);
                } else {
                    *(float2*)(g_ffn + (size_t)m * D_ + n) = make_float2(v0, v1);
                    unsigned short h0, l0, h1, l1;
                    split3(v0, h0, l0); split3(v1, h1, l1);
                    unsigned* dst = (unsigned*)(g_ffn3 + (size_t)m * (3 * D_) + 3 * n);
                    dst[0] = (unsigned)h0 | ((unsigned)l0 << 16);
                    dst[1] = (unsigned)h0 | ((unsigned)h1 << 16);
                    dst[2] = (unsigned)l1 | ((unsigned)h1 << 16);
                }
            }
        }
    }
}

// ---------------- launch ------------------------------------------------------
extern "C" void kernel_launch(void* const* d_in, const int* in_sizes, int n_in,
                              void* d_out, int out_size) {
    const float* iQ = (const float*)d_in[0];
    const float* iV = (const float*)d_in[1];
    const float* W1 = (const float*)d_in[2];
    const float* b1 = (const float*)d_in[3];
    const float* W2 = (const float*)d_in[4];
    const float* b2 = (const float*)d_in[5];
    const float* Wg = (const float*)d_in[6];
    const float* bg = (const float*)d_in[7];
    float* out = (float*)d_out;

    cudaFuncSetAttribute(k_gemm_mma<0>, cudaFuncAttributeMaxDynamicSharedMemorySize, SMEM_DYN);
    cudaFuncSetAttribute(k_gemm_mma<1>, cudaFuncAttributeMaxDynamicSharedMemorySize, SMEM_DYN);
    cudaFuncSetAttribute(k_gemm_mma<2>, cudaFuncAttributeMaxDynamicSharedMemorySize, SMEM_DYN);

    __nv_bfloat16 *w13, *w23, *wg3, *q3, *avg3, *h3, *ffn3;
    cudaGetSymbolAddress((void**)&w13,  g_W13);
    cudaGetSymbolAddress((void**)&w23,  g_W23);
    cudaGetSymbolAddress((void**)&wg3,  g_Wg3);
    cudaGetSymbolAddress((void**)&q3,   g_q3);
    cudaGetSymbolAddress((void**)&avg3, g_avg3);
    cudaGetSymbolAddress((void**)&h3,   g_h3);
    cudaGetSymbolAddress((void**)&ffn3, g_ffn3);

    // operand prep
    k_convert_iQ<<<(M_ * D_) / 256, 256>>>(iQ);
    k_convert_W<<<dim3(D_ / 64, D_ / 64), 256>>>(W1, w13, D_, D_);
    k_convert_W<<<dim3(D_ / 64, D_ / 64), 256>>>(W2, w23, D_, D_);
    k_convert_W<<<dim3(2 * D_ / 64, 2 * D_ / 64), 256>>>(Wg, wg3, 2 * D_, 2 * D_);

    // causal cumulative mean -> g_avg3
    k_partial_sums<<<dim3(B_, NCH), D_>>>(iV);
    k_exclusive_prefix<<<B_, D_>>>();
    k_cumavg<<<dim3(B_, NCH), D_>>>(iV);

    // h = relu(avg @ W1 + b1)            [K'=3072]
    k_gemm_mma<0><<<dim3(D_ / 128, M_ / 128), 256, SMEM_DYN>>>(avg3, nullptr, w13, b1, D_, 3 * D_, nullptr, nullptr);
    // ffn = h @ W2 + b2                  [K'=3072]
    k_gemm_mma<1><<<dim3(D_ / 128, M_ / 128), 256, SMEM_DYN>>>(h3, nullptr, w23, b2, D_, 3 * D_, nullptr, nullptr);
    // out = fused gate GEMM + combine    [K'=6144, paired cols]
    k_gemm_mma<2><<<dim3(D_ / 64, M_ / 128), 256, SMEM_DYN>>>(q3, ffn3, wg3, bg, 2 * D_, 6 * D_, iQ, out);
}

// round 7
// speedup vs baseline: 1.8720x; 1.0026x over previous
#include <cuda_runtime.h>
#include <cuda_bf16.h>

#define B_   4
#define S_   2048
#define D_   1024
#define M_   (B_ * S_)          // 8192
#define NCH  16
#define CH   (S_ / NCH)         // 128

// ---------------- scratch ----------------------------------------------------
// interleaved-K bf16 operands: A-side slots (hi, lo, hi), B-side slots (hi, hi, lo)
__device__ __align__(256) __nv_bfloat16 g_q3  [(size_t)M_ * 3 * D_];
__device__ __align__(256) __nv_bfloat16 g_avg3[(size_t)M_ * 3 * D_];
__device__ __align__(256) __nv_bfloat16 g_h3  [(size_t)M_ * 3 * D_];
__device__ __align__(256) __nv_bfloat16 g_ffn3[(size_t)M_ * 3 * D_];
__device__ __align__(256) __nv_bfloat16 g_W13 [(size_t)D_ * 3 * D_];        // [N, 3K]
__device__ __align__(256) __nv_bfloat16 g_W23 [(size_t)D_ * 3 * D_];
__device__ __align__(256) __nv_bfloat16 g_Wg3 [(size_t)2 * D_ * 6 * D_];
__device__ __align__(256) float g_ffn [(size_t)M_ * D_];
__device__ float g_part[B_ * NCH * D_];

// ---------------- helpers ----------------------------------------------------
__device__ __forceinline__ unsigned smem_u32(const void* p) {
    unsigned r;
    asm("{ .reg .u64 t; cvta.to.shared.u64 t, %1; cvt.u32.u64 %0, t; }" : "=r"(r) : "l"(p));
    return r;
}
__device__ __forceinline__ void split3(float x, unsigned short& h, unsigned short& l) {
    __nv_bfloat16 hb = __float2bfloat16_rn(x);
    h = __bfloat16_as_ushort(hb);
    l = __bfloat16_as_ushort(__float2bfloat16_rn(x - __bfloat162float(hb)));
}
__device__ __forceinline__ void ldsm4(unsigned& r0, unsigned& r1, unsigned& r2, unsigned& r3,
                                      unsigned addr) {
    asm volatile("ldmatrix.sync.aligned.m8n8.x4.shared.b16 {%0,%1,%2,%3}, [%4];"
                 : "=r"(r0), "=r"(r1), "=r"(r2), "=r"(r3) : "r"(addr));
}
__device__ __forceinline__ void mma16816(float* c, unsigned a0, unsigned a1, unsigned a2,
                                         unsigned a3, unsigned b0, unsigned b1) {
    asm volatile(
        "mma.sync.aligned.m16n8k16.row.col.f32.bf16.bf16.f32 "
        "{%0,%1,%2,%3}, {%4,%5,%6,%7}, {%8,%9}, {%0,%1,%2,%3};"
        : "+f"(c[0]), "+f"(c[1]), "+f"(c[2]), "+f"(c[3])
        : "r"(a0), "r"(a1), "r"(a2), "r"(a3), "r"(b0), "r"(b1));
}
// write 32 values as interleaved (hi, lo, hi) bf16 triples: 96 bf16 = 12 uint4
__device__ __forceinline__ void write_hilohi(__nv_bfloat16* dst, const float* v) {
    unsigned w[48];
#pragma unroll
    for (int p = 0; p < 16; p++) {
        unsigned short h0, l0, h1, l1;
        split3(v[2 * p],     h0, l0);
        split3(v[2 * p + 1], h1, l1);
        w[3 * p + 0] = (unsigned)h0 | ((unsigned)l0 << 16);
        w[3 * p + 1] = (unsigned)h0 | ((unsigned)h1 << 16);
        w[3 * p + 2] = (unsigned)l1 | ((unsigned)h1 << 16);
    }
    uint4* d = (uint4*)dst;
#pragma unroll
    for (int i = 0; i < 12; i++)
        d[i] = make_uint4(w[4 * i], w[4 * i + 1], w[4 * i + 2], w[4 * i + 3]);
}

// ---------------- scan: causal cumulative mean -------------------------------
__global__ void k_partial_sums(const float* __restrict__ iV) {
    int b = blockIdx.x, ch = blockIdx.y, d = threadIdx.x;
    const float* p = iV + ((size_t)b * S_ + (size_t)ch * CH) * D_ + d;
    float s = 0.f;
#pragma unroll 8
    for (int t = 0; t < CH; t++) s += p[(size_t)t * D_];
    g_part[(b * NCH + ch) * D_ + d] = s;
}

__global__ void k_exclusive_prefix() {
    int b = blockIdx.x, d = threadIdx.x;
    float run = 0.f;
#pragma unroll
    for (int ch = 0; ch < NCH; ch++) {
        int idx = (b * NCH + ch) * D_ + d;
        float v = g_part[idx];
        g_part[idx] = run;
        run += v;
    }
}

__global__ void k_cumavg(const float* __restrict__ iV) {
    int b = blockIdx.x, ch = blockIdx.y, d = threadIdx.x;
    float run = g_part[(b * NCH + ch) * D_ + d];
    const float* p = iV + ((size_t)b * S_ + (size_t)ch * CH) * D_ + d;
    size_t mrow = (size_t)b * S_ + (size_t)ch * CH;
#pragma unroll 4
    for (int t = 0; t < CH; t++) {
        run += p[(size_t)t * D_];
        int s = ch * CH + t;
        float x = run * (1.0f / (float)(s + 1));
        unsigned short h, l;
        split3(x, h, l);
        __nv_bfloat16* o = g_avg3 + (mrow + t) * (3 * D_) + 3 * d;
        o[0] = __ushort_as_bfloat16(h);
        o[1] = __ushort_as_bfloat16(l);
        o[2] = __ushort_as_bfloat16(h);
    }
}

// ---------------- conversions ------------------------------------------------
// iQ fp32 -> g_q3 interleaved, 32 elements per thread, vectorized
__global__ __launch_bounds__(256) void k_convert_iQ(const float* __restrict__ iQ) {
    size_t t = (size_t)blockIdx.x * blockDim.x + threadIdx.x;   // M_*D_/32 threads
    size_t m  = t / (D_ / 32);
    int    dq = (int)(t % (D_ / 32)) * 32;
    float v[32];
    const float4* src = (const float4*)(iQ + m * D_ + dq);
#pragma unroll
    for (int i = 0; i < 8; i++) {
        float4 x = src[i];
        v[4 * i + 0] = x.x; v[4 * i + 1] = x.y; v[4 * i + 2] = x.z; v[4 * i + 3] = x.w;
    }
    write_hilohi(g_q3 + m * (3 * D_) + 3 * dq, v);
}

// W [K,N] fp32 -> W3 [N, 3K] bf16 slots (hi, hi, lo). 64x64 tile, 256 threads.
__global__ __launch_bounds__(256) void k_convert_W(const float* __restrict__ W,
                                                   __nv_bfloat16* __restrict__ W3,
                                                   int K, int N) {
    __shared__ float t[64][65];
    const int tid = threadIdx.x;
    const int n0 = blockIdx.x * 64, k0 = blockIdx.y * 64;
    {
        const int r = tid >> 4;
        const int c4 = tid & 15;
#pragma unroll
        for (int i = 0; i < 4; i++) {
            int k = r + 16 * i;
            float4 v = *(const float4*)(W + (size_t)(k0 + k) * N + n0 + 4 * c4);
            t[k][4 * c4 + 0] = v.x;
            t[k][4 * c4 + 1] = v.y;
            t[k][4 * c4 + 2] = v.z;
            t[k][4 * c4 + 3] = v.w;
        }
    }
    __syncthreads();
    const int n = tid >> 2;
    const int kq = tid & 3;
    unsigned short s[48];
#pragma unroll
    for (int j = 0; j < 16; j++) {
        unsigned short h, l;
        split3(t[16 * kq + j][n], h, l);
        s[3 * j + 0] = h; s[3 * j + 1] = h; s[3 * j + 2] = l;
    }
    unsigned w[24];
#pragma unroll
    for (int i = 0; i < 24; i++)
        w[i] = (unsigned)s[2 * i] | ((unsigned)s[2 * i + 1] << 16);
    uint4* dst = (uint4*)(W3 + (size_t)(n0 + n) * (3 * K) + 3 * (k0 + 16 * kq));
#pragma unroll
    for (int i = 0; i < 6; i++)
        dst[i] = make_uint4(w[4 * i], w[4 * i + 1], w[4 * i + 2], w[4 * i + 3]);
}

// ---------------- HMMA bf16 GEMM (128x256 tile, 512 threads) -------------------
// SEL 0: g_avg3 @ g_W13 -> relu+b1 -> g_h3
// SEL 1: g_h3   @ g_W23 -> +b2    -> g_ffn (fp32) + g_ffn3
// SEL 2: concat(g_q3, g_ffn3) @ g_Wg3(paired cols n, n+1024) -> sigmoid ->
//        smem exchange -> out = igate*iQ + fgate*ffn
#define BM 128
#define BN 256
#define BK 64            // bf16 per K block = 128 B row
#define STAGES 3
#define A_BYTES (BM * 128)                  // 16 KB
#define B_BYTES (BN * 128)                  // 32 KB
#define STG_BYTES (A_BYTES + B_BYTES)       // 48 KB
#define SMEM_DYN (STAGES * STG_BYTES)       // 144 KB

template <int SEL>
__global__ __launch_bounds__(512, 1)
void k_gemm_mma(const __nv_bfloat16* __restrict__ A0,
                const __nv_bfloat16* __restrict__ A1,
                const __nv_bfloat16* __restrict__ Bw,
                const float* __restrict__ bias,
                int N, int K3,
                const float* __restrict__ iQf,
                float* __restrict__ out)
{
    extern __shared__ __align__(1024) char dsmem[];
    const unsigned sbase = smem_u32(dsmem);

    const int tid = threadIdx.x;
    const int warp = tid >> 5, lid = tid & 31;
    const int wm = warp >> 3;            // 0..1  -> 64 rows each
    const int wn = warp & 7;             // 0..7  -> 32 cols each
    const int m0 = blockIdx.y * BM;
    const int n0 = blockIdx.x * BN;      // SEL0/1 col base
    const int cg0 = blockIdx.x * 128;    // SEL2: gate col-pair base
    const int NB = K3 / BK;

    // loader indices: A 2 chunks/thread, B 4 chunks/thread (16B each)
    const int ar  = tid >> 2;            // 0..127
    const int ac0 = (tid & 3) * 2;
    const int br  = tid >> 1;            // 0..255
    const int bc0 = (tid & 1) * 4;

    float acc[4][4][4];
#pragma unroll
    for (int i = 0; i < 4; i++)
#pragma unroll
        for (int j = 0; j < 4; j++)
#pragma unroll
            for (int k = 0; k < 4; k++) acc[i][j][k] = 0.f;

    auto load_blk = [&](int kb, int stage) {
        unsigned sA = sbase + stage * STG_BYTES;
        unsigned sB = sA + A_BYTES;
        const __nv_bfloat16* Arow;
        if (SEL == 2 && kb >= 48)
            Arow = A1 + (size_t)(m0 + ar) * (3 * D_) + (size_t)(kb - 48) * BK;
        else
            Arow = A0 + (size_t)(m0 + ar) * (3 * D_) + (size_t)kb * BK;
        unsigned long long ag = (unsigned long long)Arow;
        unsigned asm_ = sA + ar * 128;
        const int aswz = ar & 7;
#pragma unroll
        for (int i = 0; i < 2; i++) {
            int c = ac0 + i;
            asm volatile("cp.async.cg.shared.global [%0], [%1], 16;"
                         :: "r"(asm_ + (unsigned)((c ^ aswz) << 4)), "l"(ag + c * 16) : "memory");
        }
        int gn;
        if (SEL == 2) gn = (br < 128) ? (cg0 + br) : (1024 + cg0 + br - 128);
        else          gn = n0 + br;
        const __nv_bfloat16* Brow = Bw + (size_t)gn * K3 + (size_t)kb * BK;
        unsigned long long bg2 = (unsigned long long)Brow;
        unsigned bsm = sB + br * 128;
        const int bswz = br & 7;
#pragma unroll
        for (int i = 0; i < 4; i++) {
            int c = bc0 + i;
            asm volatile("cp.async.cg.shared.global [%0], [%1], 16;"
                         :: "r"(bsm + (unsigned)((c ^ bswz) << 4)), "l"(bg2 + c * 16) : "memory");
        }
        asm volatile("cp.async.commit_group;" ::: "memory");
    };

    // ---- fragment addressing ----
    int arow[4], brow[2];
#pragma unroll
    for (int mt = 0; mt < 4; mt++)
        arow[mt] = wm * 64 + mt * 16 + (lid & 7) + ((lid >> 3) & 1) * 8;
    const int ahi = lid >> 4;
#pragma unroll
    for (int p = 0; p < 2; p++)
        brow[p] = wn * 32 + p * 16 + (lid & 7) + (lid >> 4) * 8;
    const int bhi = (lid >> 3) & 1;

    // ---- prologue ----
#pragma unroll
    for (int s = 0; s < STAGES - 1; s++) load_blk(s, s);

    for (int kb = 0; kb < NB; kb++) {
        asm volatile("cp.async.wait_group %0;" :: "n"(STAGES - 2) : "memory");
        __syncthreads();
        if (kb + STAGES - 1 < NB) load_blk(kb + STAGES - 1, (kb + STAGES - 1) % STAGES);

        unsigned sA = sbase + (kb % STAGES) * STG_BYTES;
        unsigned sB = sA + A_BYTES;
#pragma unroll
        for (int ks = 0; ks < 4; ks++) {
            unsigned a[4][4];
#pragma unroll
            for (int mt = 0; mt < 4; mt++) {
                unsigned addr = sA + arow[mt] * 128 +
                                (unsigned)(((2 * ks + ahi) ^ (arow[mt] & 7)) << 4);
                ldsm4(a[mt][0], a[mt][1], a[mt][2], a[mt][3], addr);
            }
            unsigned b[2][4];
#pragma unroll
            for (int p = 0; p < 2; p++) {
                unsigned addr = sB + brow[p] * 128 +
                                (unsigned)(((2 * ks + bhi) ^ (brow[p] & 7)) << 4);
                ldsm4(b[p][0], b[p][1], b[p][2], b[p][3], addr);
            }
#pragma unroll
            for (int mt = 0; mt < 4; mt++)
#pragma unroll
                for (int nt = 0; nt < 4; nt++)
                    mma16816(acc[mt][nt], a[mt][0], a[mt][1], a[mt][2], a[mt][3],
                             b[nt >> 1][(nt & 1) * 2], b[nt >> 1][(nt & 1) * 2 + 1]);
        }
    }

    // ---- epilogue ----
    const int gid = lid >> 2, tig = lid & 3;

    if (SEL == 2) {
        __syncthreads();
        float* gsm = (float*)dsmem;        // [128][260]
#pragma unroll
        for (int mt = 0; mt < 4; mt++) {
#pragma unroll
            for (int r2 = 0; r2 < 2; r2++) {
                const int ml = wm * 64 + mt * 16 + gid + r2 * 8;
#pragma unroll
                for (int nt = 0; nt < 4; nt++) {
                    const int nl = wn * 32 + nt * 8 + 2 * tig;
                    const int gcol = (nl < 128) ? (cg0 + nl) : (1024 + cg0 + nl - 128);
                    float2 bb = *(const float2*)(bias + gcol);
                    float v0 = acc[mt][nt][r2 * 2 + 0] + bb.x;
                    float v1 = acc[mt][nt][r2 * 2 + 1] + bb.y;
                    v0 = 1.0f / (1.0f + __expf(-v0));
                    v1 = 1.0f / (1.0f + __expf(-v1));
                    gsm[ml * 260 + nl]     = v0;
                    gsm[ml * 260 + nl + 1] = v1;
                }
            }
        }
        __syncthreads();
        // out[m, cg0 + c] = gi*iQ + gf*ffn   for c in [0,128)
        const int c4 = tid & 31;            // float4 col group 0..31
        const int r0 = tid >> 5;            // 0..15
#pragma unroll
        for (int i = 0; i < 8; i++) {
            const int r = r0 + 16 * i;
            const int col = 4 * c4;
            const size_t gidx = (size_t)(m0 + r) * D_ + cg0 + col;
            float4 q = *(const float4*)(iQf + gidx);
            float4 f = *(const float4*)(g_ffn + gidx);
            float4 gi = *(const float4*)&gsm[r * 260 + col];
            float4 gf = *(const float4*)&gsm[r * 260 + 128 + col];
            float4 o;
            o.x = gi.x * q.x + gf.x * f.x;
            o.y = gi.y * q.y + gf.y * f.y;
            o.z = gi.z * q.z + gf.z * f.z;
            o.w = gi.w * q.w + gf.w * f.w;
            *(float4*)(out + gidx) = o;
        }
        return;
    }

#pragma unroll
    for (int mt = 0; mt < 4; mt++) {
#pragma unroll
        for (int r2 = 0; r2 < 2; r2++) {
            const int m = m0 + wm * 64 + mt * 16 + gid + r2 * 8;
#pragma unroll
            for (int nt = 0; nt < 4; nt++) {
                const int n = n0 + wn * 32 + nt * 8 + 2 * tig;
                float2 bb = *(const float2*)(bias + n);
                float v0 = acc[mt][nt][r2 * 2 + 0] + bb.x;
                float v1 = acc[mt][nt][r2 * 2 + 1] + bb.y;
                if (SEL == 0) {
                    v0 = fmaxf(v0, 0.f); v1 = fmaxf(v1, 0.f);
                    unsigned short h0, l0, h1, l1;
                    split3(v0, h0, l0); split3(v1, h1, l1);
                    unsigned* dst = (unsigned*)(g_h3 + (size_t)m * (3 * D_) + 3 * n);
                    dst[0] = (unsigned)h0 | ((unsigned)l0 << 16);
                    dst[1] = (unsigned)h0 | ((unsigned)h1 << 16);
                    dst[2] = (unsigned)l1 | ((unsigned)h1 << 16);
                } else {
                    *(float2*)(g_ffn + (size_t)m * D_ + n) = make_float2(v0, v1);
                    unsigned short h0, l0, h1, l1;
                    split3(v0, h0, l0); split3(v1, h1, l1);
                    unsigned* dst = (unsigned*)(g_ffn3 + (size_t)m * (3 * D_) + 3 * n);
                    dst[0] = (unsigned)h0 | ((unsigned)l0 << 16);
                    dst[1] = (unsigned)h0 | ((unsigned)h1 << 16);
                    dst[2] = (unsigned)l1 | ((unsigned)h1 << 16);
                }
            }
        }
    }
}

// ---------------- launch ------------------------------------------------------
extern "C" void kernel_launch(void* const* d_in, const int* in_sizes, int n_in,
                              void* d_out, int out_size) {
    const float* iQ = (const float*)d_in[0];
    const float* iV = (const float*)d_in[1];
    const float* W1 = (const float*)d_in[2];
    const float* b1 = (const float*)d_in[3];
    const float* W2 = (const float*)d_in[4];
    const float* b2 = (const float*)d_in[5];
    const float* Wg = (const float*)d_in[6];
    const float* bg = (const float*)d_in[7];
    float* out = (float*)d_out;

    cudaFuncSetAttribute(k_gemm_mma<0>, cudaFuncAttributeMaxDynamicSharedMemorySize, SMEM_DYN);
    cudaFuncSetAttribute(k_gemm_mma<1>, cudaFuncAttributeMaxDynamicSharedMemorySize, SMEM_DYN);
    cudaFuncSetAttribute(k_gemm_mma<2>, cudaFuncAttributeMaxDynamicSharedMemorySize, SMEM_DYN);

    __nv_bfloat16 *w13, *w23, *wg3, *q3, *avg3, *h3, *ffn3;
    cudaGetSymbolAddress((void**)&w13,  g_W13);
    cudaGetSymbolAddress((void**)&w23,  g_W23);
    cudaGetSymbolAddress((void**)&wg3,  g_Wg3);
    cudaGetSymbolAddress((void**)&q3,   g_q3);
    cudaGetSymbolAddress((void**)&avg3, g_avg3);
    cudaGetSymbolAddress((void**)&h3,   g_h3);
    cudaGetSymbolAddress((void**)&ffn3, g_ffn3);

    // operand prep
    k_convert_iQ<<<(M_ * D_ / 32) / 256, 256>>>(iQ);
    k_convert_W<<<dim3(D_ / 64, D_ / 64), 256>>>(W1, w13, D_, D_);
    k_convert_W<<<dim3(D_ / 64, D_ / 64), 256>>>(W2, w23, D_, D_);
    k_convert_W<<<dim3(2 * D_ / 64, 2 * D_ / 64), 256>>>(Wg, wg3, 2 * D_, 2 * D_);

    // causal cumulative mean -> g_avg3
    k_partial_sums<<<dim3(B_, NCH), D_>>>(iV);
    k_exclusive_prefix<<<B_, D_>>>();
    k_cumavg<<<dim3(B_, NCH), D_>>>(iV);

    // h = relu(avg @ W1 + b1)            [K'=3072]
    k_gemm_mma<0><<<dim3(D_ / BN, M_ / BM), 512, SMEM_DYN>>>(avg3, nullptr, w13, b1, D_, 3 * D_, nullptr, nullptr);
    // ffn = h @ W2 + b2                  [K'=3072]
    k_gemm_mma<1><<<dim3(D_ / BN, M_ / BM), 512, SMEM_DYN>>>(h3, nullptr, w23, b2, D_, 3 * D_, nullptr, nullptr);
    // out = fused gate GEMM + combine    [K'=6144, paired cols]
    k_gemm_mma<2><<<dim3(2 * D_ / BN, M_ / BM), 512, SMEM_DYN>>>(q3, ffn3, wg3, bg, 2 * D_, 6 * D_, iQ, out);
}